// round 4
// baseline (speedup 1.0000x reference)
#include <cuda_runtime.h>
#include <cuda_fp16.h>
#include <cstdint>

#define R_TOT 1152
#define B_TOT 256
#define C_N 10
#define O_N 16
#define CO 160
#define I_N 8

// k1 tiling
#define TB 16              // batches per k1 block
#define K1_RC 36           // rows per k1 block
#define K1_NCH 32          // 1152/36 r-chunks

// kroute tiling
#define SEG_N 4            // row segments per batch
#define SEG_ROWS 288       // R_TOT / SEG_N
#define NW 16              // warps per kroute block
#define RWARP 18           // rows per warp (288/16)

// Scratch (device globals: allocation-free kernel_launch)
__device__ __half g_uh[(size_t)B_TOT * R_TOT * CO];          // 94.4 MB fp16, [b][r][co]
__device__ float  g_b2[(size_t)B_TOT * R_TOT * C_N];         // b after iter-1 update
__device__ float  g_spart1[(size_t)K1_NCH * B_TOT * CO];     // k1 partial s
__device__ float  g_spart2[2][(size_t)SEG_N * B_TOT * CO];   // kroute partial s

// ---------------------------------------------------------------------------
// K1: u_hat = einsum('rcoi,bri->brco') -> fp16, fused softmax(b_init) + s1.
// grid = 16 b-tiles x 32 r-chunks = 512 blocks, 160 threads (one per (c,o)).
// TB=16 halves W L2 traffic vs TB=8.
// ---------------------------------------------------------------------------
__global__ __launch_bounds__(160) void k1(const float* __restrict__ x,
                                          const float* __restrict__ W,
                                          const float* __restrict__ binit) {
    const int bt = blockIdx.x & 15;
    const int rc = blockIdx.x >> 4;          // 0..31 (36-row chunk)
    const int b0 = bt * TB;
    const int tid = threadIdx.x;             // co
    const int c = tid >> 4;
    const int r0 = rc * K1_RC;

    __shared__ float x_sm[TB][K1_RC][I_N];
    __shared__ float c_sm[TB][K1_RC][C_N];

    const float4* W4 = reinterpret_cast<const float4*>(W);
    const float4* x4 = reinterpret_cast<const float4*>(x);

    // stage x tile (float4-coalesced): TB*K1_RC*8 floats
    for (int i = tid; i < TB * K1_RC * 2; i += 160) {
        int bb = i / (K1_RC * 2);
        int rem = i - bb * (K1_RC * 2);
        reinterpret_cast<float4*>(&x_sm[bb][0][0])[rem] =
            x4[((size_t)(b0 + bb) * R_TOT + r0) * 2 + rem];
    }
    // softmax(b_init) for the TB*K1_RC (b,r) pairs
    for (int p = tid; p < TB * K1_RC; p += 160) {
        int bb = p / K1_RC;
        int rr = p - bb * K1_RC;
        const float* bp = binit + ((size_t)(b0 + bb) * R_TOT + r0 + rr) * C_N;
        float e[C_N];
        float m = bp[0];
#pragma unroll
        for (int j = 1; j < C_N; j++) m = fmaxf(m, bp[j]);
        float sum = 0.f;
#pragma unroll
        for (int j = 0; j < C_N; j++) { e[j] = expf(bp[j] - m); sum += e[j]; }
        float inv = 1.f / sum;
#pragma unroll
        for (int j = 0; j < C_N; j++) c_sm[bb][rr][j] = e[j] * inv;
    }
    __syncthreads();

    float s_acc[TB];
#pragma unroll
    for (int i = 0; i < TB; i++) s_acc[i] = 0.f;

    for (int rr = 0; rr < K1_RC; rr++) {
        const int r = r0 + rr;
        const float4* wp = W4 + ((size_t)r * CO + tid) * 2;   // W[r, c, o, :]
        const float4 wa = wp[0];
        const float4 wb = wp[1];
#pragma unroll
        for (int bb = 0; bb < TB; bb++) {
            const float4* xp = reinterpret_cast<const float4*>(&x_sm[bb][rr][0]);
            float4 xa = xp[0], xb = xp[1];
            float uh = wa.x * xa.x + wa.y * xa.y + wa.z * xa.z + wa.w * xa.w
                     + wb.x * xb.x + wb.y * xb.y + wb.z * xb.z + wb.w * xb.w;
            g_uh[((size_t)(b0 + bb) * R_TOT + r) * CO + tid] = __float2half_rn(uh);
            s_acc[bb] += c_sm[bb][rr][c] * uh;
        }
    }
#pragma unroll
    for (int bb = 0; bb < TB; bb++)
        g_spart1[((size_t)rc * B_TOT + (b0 + bb)) * CO + tid] = s_acc[bb];
}

// ---------------------------------------------------------------------------
// Fused routing pass (iter = 2 or 3), single pass over u_hat, warp-per-row.
// Lane l of a warp holds half2 columns {l, 32+l, 64+l} of a row; cap = j/8
// aligns with 8-lane groups -> agreement via segmented shfl butterflies,
// softmax via warp butterflies (8x group redundancy divided out exactly),
// and the same registers feed the s accumulation. u_hat read ONCE, from L2.
// grid = 256 b x 4 segs = 1024 blocks, 512 threads (16 warps x 18 rows).
// ---------------------------------------------------------------------------
__global__ __launch_bounds__(512) void kroute(const float* __restrict__ binit, int iter) {
    __shared__ float vs[CO];
    __shared__ float sacc[NW][CO];

    const int b   = blockIdx.x >> 2;
    const int seg = blockIdx.x & 3;
    const int tid = threadIdx.x;
    const int w = tid >> 5, l = tid & 31;

    // v = squash(sum of prev partials) -- threads 0..159, deterministic
    if (tid < CO) {
        float s = 0.f;
        if (iter == 2) {
#pragma unroll
            for (int p = 0; p < K1_NCH; p++)
                s += g_spart1[((size_t)p * B_TOT + b) * CO + tid];
        } else {
#pragma unroll
            for (int p = 0; p < SEG_N; p++)
                s += g_spart2[0][((size_t)p * B_TOT + b) * CO + tid];
        }
        float n = s * s;
#pragma unroll
        for (int off = 8; off >= 1; off >>= 1)
            n += __shfl_xor_sync(0xffffffffu, n, off);
        float scale = (n / (1.f + n)) * rsqrtf(n + 1e-8f);
        vs[tid] = scale * s;
    }
    __syncthreads();

    const int g = l >> 3;
    const int j0 = l, j1 = 32 + l, j2 = 64 + l;   // half2 column indices
    const bool k2ok = (l < 16);                    // j2 < 80 only for l < 16
    const float2* vs2 = reinterpret_cast<const float2*>(vs);
    const float2 v0 = vs2[j0];
    const float2 v1 = vs2[j1];
    const float2 v2 = k2ok ? vs2[j2] : make_float2(0.f, 0.f);
    const int cap0 = g, cap1 = 4 + g, cap2 = 8 + g;

    float2 acc0 = make_float2(0.f, 0.f);
    float2 acc1 = make_float2(0.f, 0.f);
    float2 acc2 = make_float2(0.f, 0.f);

    const int r0 = seg * SEG_ROWS + w * RWARP;
    const float* bsrc = (iter == 2) ? binit : g_b2;

#pragma unroll 3
    for (int i = 0; i < RWARP; i++) {
        const int r = r0 + i;
        const size_t row = (size_t)b * R_TOT + r;
        const __half2* up = reinterpret_cast<const __half2*>(g_uh + row * CO);
        __half2 h0 = up[j0];
        __half2 h1 = up[j1];
        __half2 h2 = __half2half2(__ushort_as_half((unsigned short)0));
        if (k2ok) h2 = up[j2];
        float2 f0 = __half22float2(h0);
        float2 f1 = __half22float2(h1);
        float2 f2 = __half22float2(h2);

        // per-lane agreement partials
        float a0 = f0.x * v0.x + f0.y * v0.y;
        float a1 = f1.x * v1.x + f1.y * v1.y;
        float a2 = f2.x * v2.x + f2.y * v2.y;
        // segmented sum within 8-lane groups (stays inside group via xor<=4)
#pragma unroll
        for (int off = 1; off <= 4; off <<= 1) {
            a0 += __shfl_xor_sync(0xffffffffu, a0, off);
            a1 += __shfl_xor_sync(0xffffffffu, a1, off);
            a2 += __shfl_xor_sync(0xffffffffu, a2, off);
        }
        const float* bp = bsrc + row * C_N;
        float bv0 = a0 + __ldg(bp + cap0);
        float bv1 = a1 + __ldg(bp + cap1);
        float bv2 = k2ok ? (a2 + __ldg(bp + cap2)) : -1e30f;
        if (iter == 2 && (l & 7) == 0) {      // persist b2 (one lane per group)
            float* bo = g_b2 + row * C_N;
            bo[cap0] = bv0;
            bo[cap1] = bv1;
            if (k2ok) bo[cap2] = bv2;
        }
        // softmax over the 10 caps (values replicated 8x per group)
        float m = fmaxf(fmaxf(bv0, bv1), bv2);
#pragma unroll
        for (int off = 1; off <= 16; off <<= 1)
            m = fmaxf(m, __shfl_xor_sync(0xffffffffu, m, off));
        float e0 = __expf(bv0 - m);
        float e1 = __expf(bv1 - m);
        float e2 = k2ok ? __expf(bv2 - m) : 0.f;
        float ps = e0 + e1 + e2;
#pragma unroll
        for (int off = 1; off <= 16; off <<= 1)
            ps += __shfl_xor_sync(0xffffffffu, ps, off);
        const float inv = __fdividef(8.f, ps);   // divide out 8x replication
        float c0 = e0 * inv, c1 = e1 * inv, c2 = e2 * inv;

        // s accumulation from the SAME registers (u_hat read once)
        acc0.x = fmaf(c0, f0.x, acc0.x); acc0.y = fmaf(c0, f0.y, acc0.y);
        acc1.x = fmaf(c1, f1.x, acc1.x); acc1.y = fmaf(c1, f1.y, acc1.y);
        acc2.x = fmaf(c2, f2.x, acc2.x); acc2.y = fmaf(c2, f2.y, acc2.y);
    }

    // per-warp partial vectors -> SMEM -> deterministic cross-warp reduce
    float2* srow = reinterpret_cast<float2*>(&sacc[w][0]);
    srow[j0] = acc0;
    srow[j1] = acc1;
    if (k2ok) srow[j2] = acc2;
    __syncthreads();
    if (tid < CO) {
        float s = 0.f;
#pragma unroll
        for (int ww = 0; ww < NW; ww++) s += sacc[ww][tid];
        const int slot = (iter == 2) ? 0 : 1;
        g_spart2[slot][((size_t)seg * B_TOT + b) * CO + tid] = s;
    }
}

// ---------------------------------------------------------------------------
// Final squash of iter-3 partials -> d_out. grid=256 (b), 160 threads (co).
// ---------------------------------------------------------------------------
__global__ __launch_bounds__(160) void ksquash(float* __restrict__ out) {
    const int b = blockIdx.x;
    const int tid = threadIdx.x;
    float s = 0.f;
#pragma unroll
    for (int p = 0; p < SEG_N; p++)
        s += g_spart2[1][((size_t)p * B_TOT + b) * CO + tid];
    float n = s * s;
#pragma unroll
    for (int off = 8; off >= 1; off >>= 1)
        n += __shfl_xor_sync(0xffffffffu, n, off);
    float scale = (n / (1.f + n)) * rsqrtf(n + 1e-8f);
    out[(size_t)b * CO + tid] = scale * s;
}

// ---------------------------------------------------------------------------
extern "C" void kernel_launch(void* const* d_in, const int* in_sizes, int n_in,
                              void* d_out, int out_size) {
    const float *x = nullptr, *W = nullptr, *binit = nullptr;
    for (int i = 0; i < n_in; i++) {
        if (in_sizes[i] == B_TOT * R_TOT * I_N)          x     = (const float*)d_in[i];
        else if (in_sizes[i] == R_TOT * C_N * O_N * I_N) W     = (const float*)d_in[i];
        else if (in_sizes[i] == B_TOT * R_TOT * C_N)     binit = (const float*)d_in[i];
    }
    float* out = (float*)d_out;

    // iter 1: u_hat (fp16) + s1 partials
    k1<<<512, 160>>>(x, W, binit);
    // iter 2: v1 (in-block) + agreement + b2 + softmax + s2
    kroute<<<1024, 512>>>(binit, 2);
    // iter 3: v2 (in-block) + agreement + softmax + s3
    kroute<<<1024, 512>>>(binit, 3);
    // final squash -> out
    ksquash<<<256, 160>>>(out);
}

// round 5
// speedup vs baseline: 1.4516x; 1.4516x over previous
#include <cuda_runtime.h>
#include <cuda_fp16.h>
#include <cstdint>

#define R_TOT 1152
#define B_TOT 256
#define C_N 10
#define O_N 16
#define CO 160
#define I_N 8

// kroute tiling
#define NCH_R 8            // route chunks per batch
#define RCHK 144           // rows per route chunk
#define PAD_H 170          // fp16 row stride (340B = 85 words, odd -> conflict-free)
#define TILE_H (RCHK * PAD_H)          // 24480 halves
#define TILE_BYTES (TILE_H * 2)        // 48960 (16B multiple)
#define RT_THREADS 320

// k1 tiling
#define TB 8               // batches per k1 block
#define K1_RC 36           // rows per k1 block
#define K1_NCH 32          // 1152/36 r-chunks

// Scratch (device globals: allocation-free kernel_launch)
__device__ __half g_uh[(size_t)B_TOT * NCH_R * TILE_H];      // ~100 MB fp16 (fits L2)
__device__ float  g_b2[(size_t)B_TOT * R_TOT * C_N];         // b after iter-1 update
__device__ float  g_spart1[(size_t)K1_NCH * B_TOT * CO];     // k1 partial s
__device__ float  g_spart2[2][(size_t)NCH_R * B_TOT * CO];   // kroute partial s

__device__ __forceinline__ uint32_t smem_u32(const void* p) {
    uint32_t a;
    asm("{ .reg .u64 t; cvta.to.shared.u64 t, %1; cvt.u32.u64 %0, t; }" : "=r"(a) : "l"(p));
    return a;
}

// ---------------------------------------------------------------------------
// K1 (identical to the 146us round-3 version): u_hat -> fp16 tiles, fused
// softmax(b_init) + s1 partials. grid = 32 b-tiles x 32 r-chunks = 1024
// blocks, 160 threads (one per (c,o)).
// ---------------------------------------------------------------------------
__global__ __launch_bounds__(160) void k1(const float* __restrict__ x,
                                          const float* __restrict__ W,
                                          const float* __restrict__ binit) {
    const int bt = blockIdx.x & 31;
    const int rc = blockIdx.x >> 5;          // 0..31 (36-row chunk)
    const int b0 = bt * TB;
    const int tid = threadIdx.x;             // co
    const int c = tid >> 4;
    const int r0 = rc * K1_RC;
    const int chk_g = rc >> 2;               // 144-row tile id

    __shared__ float x_sm[TB][K1_RC][I_N];
    __shared__ float c_sm[TB][K1_RC][C_N];

    const float4* W4 = reinterpret_cast<const float4*>(W);
    const float4* x4 = reinterpret_cast<const float4*>(x);

    for (int i = tid; i < TB * K1_RC * 2; i += 160) {
        int bb = i / (K1_RC * 2);
        int rem = i - bb * (K1_RC * 2);
        reinterpret_cast<float4*>(&x_sm[bb][0][0])[rem] =
            x4[((size_t)(b0 + bb) * R_TOT + r0) * 2 + rem];
    }
    for (int p = tid; p < TB * K1_RC; p += 160) {
        int bb = p / K1_RC;
        int rr = p - bb * K1_RC;
        const float* bp = binit + ((size_t)(b0 + bb) * R_TOT + r0 + rr) * C_N;
        float e[C_N];
        float m = bp[0];
#pragma unroll
        for (int j = 1; j < C_N; j++) m = fmaxf(m, bp[j]);
        float sum = 0.f;
#pragma unroll
        for (int j = 0; j < C_N; j++) { e[j] = expf(bp[j] - m); sum += e[j]; }
        float inv = 1.f / sum;
#pragma unroll
        for (int j = 0; j < C_N; j++) c_sm[bb][rr][j] = e[j] * inv;
    }
    __syncthreads();

    float s_acc[TB];
#pragma unroll
    for (int i = 0; i < TB; i++) s_acc[i] = 0.f;

    for (int rr = 0; rr < K1_RC; rr++) {
        const int r = r0 + rr;
        const float4* wp = W4 + ((size_t)r * CO + tid) * 2;   // W[r, c, o, :]
        const float4 wa = wp[0];
        const float4 wb = wp[1];
        const int rin = r - chk_g * RCHK;
#pragma unroll
        for (int bb = 0; bb < TB; bb++) {
            const float4* xp = reinterpret_cast<const float4*>(&x_sm[bb][rr][0]);
            float4 xa = xp[0], xb = xp[1];
            float uh = wa.x * xa.x + wa.y * xa.y + wa.z * xa.z + wa.w * xa.w
                     + wb.x * xb.x + wb.y * xb.y + wb.z * xb.z + wb.w * xb.w;
            g_uh[((size_t)(b0 + bb) * NCH_R + chk_g) * TILE_H +
                 (size_t)rin * PAD_H + tid] = __float2half_rn(uh);
            s_acc[bb] += c_sm[bb][rr][c] * uh;
        }
    }
#pragma unroll
    for (int bb = 0; bb < TB; bb++)
        g_spart1[((size_t)rc * B_TOT + (b0 + bb)) * CO + tid] = s_acc[bb];
}

// ---------------------------------------------------------------------------
// Fused routing pass (iter = 2 or 3). Round-3 structure, but 320 threads:
// phase A runs 2 threads/row (288 active), phase B splits rows into two
// halves across the 2x160 thread groups. 3 blocks/SM -> 30 warps/SM.
// grid = 256 b x 8 chunks = 2048 blocks.
// ---------------------------------------------------------------------------
__global__ __launch_bounds__(RT_THREADS) void kroute(const float* __restrict__ binit,
                                                     int iter) {
    extern __shared__ __align__(16) char smem_raw[];
    __half* uh = reinterpret_cast<__half*>(smem_raw);             // TILE_H halves
    float* cT  = reinterpret_cast<float*>(smem_raw + TILE_BYTES); // [C_N][RCHK]
    float* vs  = cT + C_N * RCHK;                                 // CO
    float* sp  = vs + CO;                                         // [2][CO]
    __shared__ __align__(8) unsigned long long mbar;

    const int b   = blockIdx.x >> 3;
    const int chk = blockIdx.x & 7;
    const int tid = threadIdx.x;

    const uint32_t uh_s = smem_u32(uh);
    const uint32_t mb_s = smem_u32(&mbar);

    if (tid == 0) {
        asm volatile("mbarrier.init.shared.b64 [%0], 1;" :: "r"(mb_s) : "memory");
    }
    __syncthreads();
    if (tid == 0) {
        asm volatile("mbarrier.arrive.expect_tx.shared.b64 _, [%0], %1;"
                     :: "r"(mb_s), "r"((uint32_t)TILE_BYTES) : "memory");
        const __half* src = g_uh + ((size_t)b * NCH_R + chk) * TILE_H;
        asm volatile("cp.async.bulk.shared::cta.global.mbarrier::complete_tx::bytes "
                     "[%0], [%1], %2, [%3];"
                     :: "r"(uh_s), "l"(src), "r"((uint32_t)TILE_BYTES), "r"(mb_s)
                     : "memory");
    }

    // Overlap with bulk copy: recompute v = squash(sum of prev partials).
    if (tid < CO) {
        float s = 0.f;
        if (iter == 2) {
#pragma unroll
            for (int p = 0; p < K1_NCH; p++)
                s += g_spart1[((size_t)p * B_TOT + b) * CO + tid];
        } else {
#pragma unroll
            for (int p = 0; p < NCH_R; p++)
                s += g_spart2[0][((size_t)p * B_TOT + b) * CO + tid];
        }
        float n = s * s;
#pragma unroll
        for (int off = 8; off >= 1; off >>= 1)
            n += __shfl_xor_sync(0xffffffffu, n, off);
        float scale = (n / (1.f + n)) * rsqrtf(n + 1e-8f);
        vs[tid] = scale * s;
    }
    __syncthreads();

    // wait for bulk copy (phase 0)
    asm volatile(
        "{\n\t.reg .pred P;\n\t"
        "W_%=: mbarrier.try_wait.parity.shared.b64 P, [%0], 0;\n\t"
        "@!P bra W_%=;\n\t}"
        :: "r"(mb_s) : "memory");

    // Phase A: agreement + b update + softmax. 2 threads per row, 5 caps each.
    if (tid < 2 * RCHK) {
        const int row = tid >> 1;
        const int c0  = (tid & 1) * 5;
        const int r   = chk * RCHK + row;
        const float* bin = (iter == 2) ? (binit + ((size_t)b * R_TOT + r) * C_N)
                                       : (g_b2  + ((size_t)b * R_TOT + r) * C_N);
        const __half2* urow = reinterpret_cast<const __half2*>(uh + row * PAD_H);
        float bv[5];
#pragma unroll
        for (int j = 0; j < 5; j++) {
            const int cc = c0 + j;
            float a = 0.f;
#pragma unroll
            for (int k = 0; k < 8; k++) {
                float2 f = __half22float2(urow[cc * 8 + k]);
                a = fmaf(f.x, vs[cc * 16 + 2 * k], a);
                a = fmaf(f.y, vs[cc * 16 + 2 * k + 1], a);
            }
            bv[j] = bin[cc] + a;
        }
        if (iter == 2) {  // persist b2 for iteration 3
            float* bo = g_b2 + ((size_t)b * R_TOT + r) * C_N;
#pragma unroll
            for (int j = 0; j < 5; j++) bo[c0 + j] = bv[j];
        }
        float m = bv[0];
#pragma unroll
        for (int j = 1; j < 5; j++) m = fmaxf(m, bv[j]);
        m = fmaxf(m, __shfl_xor_sync(0xffffffffu, m, 1));
        float e[5], ps = 0.f;
#pragma unroll
        for (int j = 0; j < 5; j++) { e[j] = expf(bv[j] - m); ps += e[j]; }
        ps += __shfl_xor_sync(0xffffffffu, ps, 1);
        const float inv = 1.f / ps;
#pragma unroll
        for (int j = 0; j < 5; j++) cT[(c0 + j) * RCHK + row] = e[j] * inv;
    }
    __syncthreads();

    // Phase B: s partial; 2 groups of 160 threads, each does 72 rows.
    {
        const int grp = tid / CO;              // 0 or 1
        const int col = tid - grp * CO;        // (c,o)
        const int cc  = col >> 4;
        const float* crow = cT + cc * RCHK + grp * (RCHK / 2);
        const __half* ucol = uh + (size_t)grp * (RCHK / 2) * PAD_H + col;
        float acc = 0.f;
#pragma unroll 4
        for (int r = 0; r < RCHK / 2; r++)
            acc = fmaf(crow[r], __half2float(ucol[r * PAD_H]), acc);
        sp[grp * CO + col] = acc;
    }
    __syncthreads();
    if (tid < CO) {
        const int slot = (iter == 2) ? 0 : 1;
        g_spart2[slot][((size_t)chk * B_TOT + b) * CO + tid] = sp[tid] + sp[CO + tid];
    }
}

// ---------------------------------------------------------------------------
// Final squash of iter-3 partials -> d_out. grid=256 (b), 160 threads (co).
// ---------------------------------------------------------------------------
__global__ __launch_bounds__(160) void ksquash(float* __restrict__ out) {
    const int b = blockIdx.x;
    const int tid = threadIdx.x;
    float s = 0.f;
#pragma unroll
    for (int p = 0; p < NCH_R; p++)
        s += g_spart2[1][((size_t)p * B_TOT + b) * CO + tid];
    float n = s * s;
#pragma unroll
    for (int off = 8; off >= 1; off >>= 1)
        n += __shfl_xor_sync(0xffffffffu, n, off);
    float scale = (n / (1.f + n)) * rsqrtf(n + 1e-8f);
    out[(size_t)b * CO + tid] = scale * s;
}

// ---------------------------------------------------------------------------
extern "C" void kernel_launch(void* const* d_in, const int* in_sizes, int n_in,
                              void* d_out, int out_size) {
    const float *x = nullptr, *W = nullptr, *binit = nullptr;
    for (int i = 0; i < n_in; i++) {
        if (in_sizes[i] == B_TOT * R_TOT * I_N)          x     = (const float*)d_in[i];
        else if (in_sizes[i] == R_TOT * C_N * O_N * I_N) W     = (const float*)d_in[i];
        else if (in_sizes[i] == B_TOT * R_TOT * C_N)     binit = (const float*)d_in[i];
    }
    float* out = (float*)d_out;

    const int SMEM_ROUTE = TILE_BYTES + (C_N * RCHK + CO + 2 * CO) * (int)sizeof(float);
    cudaFuncSetAttribute(kroute, cudaFuncAttributeMaxDynamicSharedMemorySize, SMEM_ROUTE);

    // iter 1: u_hat (fp16) + s1 partials
    k1<<<1024, 160>>>(x, W, binit);
    // iter 2: v1 (in-block) + agreement + b2 + softmax + s2
    kroute<<<2048, RT_THREADS, SMEM_ROUTE>>>(binit, 2);
    // iter 3: v2 (in-block) + agreement + softmax + s3
    kroute<<<2048, RT_THREADS, SMEM_ROUTE>>>(binit, 3);
    // final squash -> out
    ksquash<<<256, 160>>>(out);
}

// round 6
// speedup vs baseline: 1.5813x; 1.0893x over previous
#include <cuda_runtime.h>
#include <cuda_fp16.h>
#include <cstdint>

#define R_TOT 1152
#define B_TOT 256
#define C_N 10
#define O_N 16
#define CO 160
#define I_N 8

// kroute tiling
#define NCH_R 8            // route chunks per batch
#define RCHK 144           // rows per route chunk
#define PAD_H 170          // fp16 row stride (340B, odd halves -> conflict-free)
#define TILE_H (RCHK * PAD_H)          // 24480 halves
#define TILE_BYTES (TILE_H * 2)        // 48960 (16B multiple)

// k1 tiling
#define TB 16              // batches per k1 block (halves W L2 traffic vs 8)
#define K1_RC 36           // rows per k1 block
#define K1_NCH 32          // 1152/36 r-chunks

// Scratch (device globals: allocation-free kernel_launch)
__device__ __half g_uh[(size_t)B_TOT * NCH_R * TILE_H];      // ~100 MB fp16 (fits L2)
__device__ float  g_b2[(size_t)B_TOT * R_TOT * C_N];         // b after iter-1 update
__device__ float  g_spart1[(size_t)K1_NCH * B_TOT * CO];     // k1 partial s
__device__ float  g_spart2[2][(size_t)NCH_R * B_TOT * CO];   // kroute partial s
__device__ int    g_cnt[B_TOT];                              // last-block counters (reset by consumer)

__device__ __forceinline__ uint32_t smem_u32(const void* p) {
    uint32_t a;
    asm("{ .reg .u64 t; cvta.to.shared.u64 t, %1; cvt.u32.u64 %0, t; }" : "=r"(a) : "l"(p));
    return a;
}

// ---------------------------------------------------------------------------
// K1: u_hat -> fp16 padded tiles, fused softmax(b_init) + s1 partials.
// grid = 16 b-tiles x 32 r-chunks = 512 blocks, 160 threads (one per (c,o)).
// TB=16: W read once per 16 batches -> 94MB total W L2 traffic.
// ---------------------------------------------------------------------------
__global__ __launch_bounds__(160) void k1(const float* __restrict__ x,
                                          const float* __restrict__ W,
                                          const float* __restrict__ binit) {
    const int bt = blockIdx.x & 15;
    const int rc = blockIdx.x >> 4;          // 0..31 (36-row chunk)
    const int b0 = bt * TB;
    const int tid = threadIdx.x;             // co
    const int c = tid >> 4;
    const int r0 = rc * K1_RC;
    const int chk_g = rc >> 2;               // 144-row tile id
    const int rin0 = (rc & 3) * K1_RC;       // row offset within tile

    __shared__ float x_sm[TB][K1_RC][I_N];
    __shared__ float c_sm[TB][K1_RC][C_N];

    const float4* W4 = reinterpret_cast<const float4*>(W);
    const float4* x4 = reinterpret_cast<const float4*>(x);

    // stage x tile (float4-coalesced): TB*K1_RC*8 floats
    for (int i = tid; i < TB * K1_RC * 2; i += 160) {
        int bb = i / (K1_RC * 2);
        int rem = i - bb * (K1_RC * 2);
        reinterpret_cast<float4*>(&x_sm[bb][0][0])[rem] =
            x4[((size_t)(b0 + bb) * R_TOT + r0) * 2 + rem];
    }
    // softmax(b_init) for the TB*K1_RC (b,r) pairs
    for (int p = tid; p < TB * K1_RC; p += 160) {
        int bb = p / K1_RC;
        int rr = p - bb * K1_RC;
        const float* bp = binit + ((size_t)(b0 + bb) * R_TOT + r0 + rr) * C_N;
        float e[C_N];
        float m = bp[0];
#pragma unroll
        for (int j = 1; j < C_N; j++) m = fmaxf(m, bp[j]);
        float sum = 0.f;
#pragma unroll
        for (int j = 0; j < C_N; j++) { e[j] = expf(bp[j] - m); sum += e[j]; }
        float inv = 1.f / sum;
#pragma unroll
        for (int j = 0; j < C_N; j++) c_sm[bb][rr][j] = e[j] * inv;
    }
    __syncthreads();

    float s_acc[TB];
#pragma unroll
    for (int i = 0; i < TB; i++) s_acc[i] = 0.f;

    for (int rr = 0; rr < K1_RC; rr++) {
        const int r = r0 + rr;
        const float4* wp = W4 + ((size_t)r * CO + tid) * 2;   // W[r, c, o, :]
        const float4 wa = wp[0];
        const float4 wb = wp[1];
        const int rin = rin0 + rr;
#pragma unroll
        for (int bb = 0; bb < TB; bb++) {
            const float4* xp = reinterpret_cast<const float4*>(&x_sm[bb][rr][0]);
            float4 xa = xp[0], xb = xp[1];
            float uh = wa.x * xa.x + wa.y * xa.y + wa.z * xa.z + wa.w * xa.w
                     + wb.x * xb.x + wb.y * xb.y + wb.z * xb.z + wb.w * xb.w;
            g_uh[((size_t)(b0 + bb) * NCH_R + chk_g) * TILE_H +
                 (size_t)rin * PAD_H + tid] = __float2half_rn(uh);
            s_acc[bb] += c_sm[bb][rr][c] * uh;
        }
    }
#pragma unroll
    for (int bb = 0; bb < TB; bb++)
        g_spart1[((size_t)rc * B_TOT + (b0 + bb)) * CO + tid] = s_acc[bb];
}

// ---------------------------------------------------------------------------
// Fused routing pass (iter = 2 or 3). Round-3 structure (160 threads):
// bulk-copy 48.96KB fp16 tile, overlap with in-block v recompute, then
// agreement -> b update -> softmax -> partial s_next. In iter 3, the last
// block per batch (atomic counter) also performs the final squash -> out.
// grid = 256 b x 8 chunks = 2048 blocks.
// ---------------------------------------------------------------------------
__global__ __launch_bounds__(160) void kroute(const float* __restrict__ binit,
                                              float* __restrict__ out, int iter) {
    extern __shared__ __align__(16) char smem_raw[];
    __half* uh = reinterpret_cast<__half*>(smem_raw);             // TILE_H halves
    float* cT  = reinterpret_cast<float*>(smem_raw + TILE_BYTES); // [C_N][RCHK]
    float* vs  = cT + C_N * RCHK;                                 // CO
    __shared__ __align__(8) unsigned long long mbar;
    __shared__ int is_last;

    const int b   = blockIdx.x >> 3;
    const int chk = blockIdx.x & 7;
    const int tid = threadIdx.x;

    const uint32_t uh_s = smem_u32(uh);
    const uint32_t mb_s = smem_u32(&mbar);

    // tid0: init + expect + launch bulk copy immediately (same-thread ordered;
    // other threads' visibility of the init is covered by the sync below).
    if (tid == 0) {
        asm volatile("mbarrier.init.shared.b64 [%0], 1;" :: "r"(mb_s) : "memory");
        asm volatile("mbarrier.arrive.expect_tx.shared.b64 _, [%0], %1;"
                     :: "r"(mb_s), "r"((uint32_t)TILE_BYTES) : "memory");
        const __half* src = g_uh + ((size_t)b * NCH_R + chk) * TILE_H;
        asm volatile("cp.async.bulk.shared::cta.global.mbarrier::complete_tx::bytes "
                     "[%0], [%1], %2, [%3];"
                     :: "r"(uh_s), "l"(src), "r"((uint32_t)TILE_BYTES), "r"(mb_s)
                     : "memory");
    }

    // Overlap with bulk copy: recompute v = squash(sum of prev partials).
    if (tid < CO) {
        float s = 0.f;
        if (iter == 2) {
#pragma unroll
            for (int p = 0; p < K1_NCH; p++)
                s += g_spart1[((size_t)p * B_TOT + b) * CO + tid];
        } else {
#pragma unroll
            for (int p = 0; p < NCH_R; p++)
                s += g_spart2[0][((size_t)p * B_TOT + b) * CO + tid];
        }
        float n = s * s;
#pragma unroll
        for (int off = 8; off >= 1; off >>= 1)
            n += __shfl_xor_sync(0xffffffffu, n, off);
        float scale = (n / (1.f + n)) * rsqrtf(n + 1e-8f);
        vs[tid] = scale * s;
    }
    __syncthreads();

    // wait for bulk copy (phase 0)
    asm volatile(
        "{\n\t.reg .pred P;\n\t"
        "W_%=: mbarrier.try_wait.parity.shared.b64 P, [%0], 0;\n\t"
        "@!P bra W_%=;\n\t}"
        :: "r"(mb_s) : "memory");

    // Phase A: agreement + b update + softmax. 1 thread per row.
    if (tid < RCHK) {
        const int r = chk * RCHK + tid;
        const float* bin = (iter == 2) ? (binit + ((size_t)b * R_TOT + r) * C_N)
                                       : (g_b2  + ((size_t)b * R_TOT + r) * C_N);
        const __half2* urow = reinterpret_cast<const __half2*>(uh + tid * PAD_H);
        float bv[C_N];
#pragma unroll
        for (int cc = 0; cc < C_N; cc++) {
            float a = 0.f;
#pragma unroll
            for (int k = 0; k < 8; k++) {
                float2 f = __half22float2(urow[cc * 8 + k]);
                a = fmaf(f.x, vs[cc * 16 + 2 * k], a);
                a = fmaf(f.y, vs[cc * 16 + 2 * k + 1], a);
            }
            bv[cc] = bin[cc] + a;
        }
        if (iter == 2) {  // persist b2 for iteration 3
            float* bo = g_b2 + ((size_t)b * R_TOT + r) * C_N;
#pragma unroll
            for (int cc = 0; cc < C_N; cc++) bo[cc] = bv[cc];
        }
        float m = bv[0];
#pragma unroll
        for (int cc = 1; cc < C_N; cc++) m = fmaxf(m, bv[cc]);
        float e[C_N], sum = 0.f;
#pragma unroll
        for (int cc = 0; cc < C_N; cc++) { e[cc] = expf(bv[cc] - m); sum += e[cc]; }
        float inv = 1.f / sum;
#pragma unroll
        for (int cc = 0; cc < C_N; cc++) cT[cc * RCHK + tid] = e[cc] * inv;
    }
    __syncthreads();

    // Phase B: s partial; thread = (c,o), loop rows.
    {
        const int cc = tid >> 4;
        const float* crow = cT + cc * RCHK;
        float acc = 0.f;
#pragma unroll 4
        for (int r = 0; r < RCHK; r++)
            acc = fmaf(crow[r], __half2float(uh[r * PAD_H + tid]), acc);
        const int slot = (iter == 2) ? 0 : 1;
        g_spart2[slot][((size_t)chk * B_TOT + b) * CO + tid] = acc;
    }

    // Iter 3: last block per batch performs the final squash -> out.
    if (iter == 3) {
        __threadfence();
        __syncthreads();
        if (tid == 0) {
            int prev = atomicAdd(&g_cnt[b], 1);
            is_last = (prev == NCH_R - 1);
        }
        __syncthreads();
        if (is_last) {
            __threadfence();   // acquire others' partial writes
            if (tid < CO) {
                float s = 0.f;
#pragma unroll
                for (int p = 0; p < NCH_R; p++)
                    s += g_spart2[1][((size_t)p * B_TOT + b) * CO + tid];
                float n = s * s;
#pragma unroll
                for (int off = 8; off >= 1; off >>= 1)
                    n += __shfl_xor_sync(0xffffffffu, n, off);
                float scale = (n / (1.f + n)) * rsqrtf(n + 1e-8f);
                out[(size_t)b * CO + tid] = scale * s;
            }
            if (tid == 0) g_cnt[b] = 0;   // reset for next graph replay
        }
    }
}

// ---------------------------------------------------------------------------
extern "C" void kernel_launch(void* const* d_in, const int* in_sizes, int n_in,
                              void* d_out, int out_size) {
    const float *x = nullptr, *W = nullptr, *binit = nullptr;
    for (int i = 0; i < n_in; i++) {
        if (in_sizes[i] == B_TOT * R_TOT * I_N)          x     = (const float*)d_in[i];
        else if (in_sizes[i] == R_TOT * C_N * O_N * I_N) W     = (const float*)d_in[i];
        else if (in_sizes[i] == B_TOT * R_TOT * C_N)     binit = (const float*)d_in[i];
    }
    float* out = (float*)d_out;

    const int SMEM_ROUTE = TILE_BYTES + (C_N * RCHK + CO) * (int)sizeof(float);
    cudaFuncSetAttribute(kroute, cudaFuncAttributeMaxDynamicSharedMemorySize, SMEM_ROUTE);

    // iter 1: u_hat (fp16) + s1 partials
    k1<<<512, 160>>>(x, W, binit);
    // iter 2: v1 (in-block) + agreement + b2 + softmax + s2
    kroute<<<2048, 160, SMEM_ROUTE>>>(binit, out, 2);
    // iter 3: v2 (in-block) + agreement + softmax + s3 + fused final squash
    kroute<<<2048, 160, SMEM_ROUTE>>>(binit, out, 3);
}